// round 2
// baseline (speedup 1.0000x reference)
#include <cuda_runtime.h>
#include <math.h>

#define BB 8
#define C  64
#define HH 128
#define WW 128
#define HW (HH*WW)
#define CO 128
#define KK 9

// ---------------- scratch (device globals; no allocation) ----------------
__device__ float g_xp [BB*C*HW];   // pre-conv output, NCHW
__device__ float g_xph[BB*HW*C];   // pre-conv output, NHWC (for gathers)
__device__ float g_py [BB*KK*HW];  // absolute sample y coord per (b,kk,pix)
__device__ float g_px [BB*KK*HW];  // absolute sample x coord
__device__ float g_m  [BB*KK*HW];  // modulation mask (2*sigmoid)
__device__ float g_wt [KK*C*CO];   // reg_w transposed to [kk][ci][co]

// ---------------- packed f32x2 helpers (sm_100+ FFMA2 path) ---------------
__device__ __forceinline__ unsigned long long f2_fma(unsigned long long a,
                                                     unsigned long long b,
                                                     unsigned long long c)
{
    unsigned long long d;
    asm("fma.rn.f32x2 %0, %1, %2, %3;" : "=l"(d) : "l"(a), "l"(b), "l"(c));
    return d;
}
__device__ __forceinline__ unsigned long long f2_dup(float x)
{
    unsigned long long d;
    asm("mov.b64 %0, {%1, %1};" : "=l"(d) : "f"(x));
    return d;
}
__device__ __forceinline__ void f2_unpack(unsigned long long v, float& lo, float& hi)
{
    asm("mov.b64 {%0, %1}, %2;" : "=f"(lo), "=f"(hi) : "l"(v));
}

// ---------------- K1: 1x1 conv, write NCHW + NHWC -----------------------
__global__ __launch_bounds__(256) void k1_pre(const float* __restrict__ x,
                                              const float* __restrict__ pw,
                                              const float* __restrict__ pb)
{
    __shared__ float ws[C*C];
    int b = blockIdx.y;
    int p = blockIdx.x * 256 + threadIdx.x;
    for (int i = threadIdx.x; i < C*C; i += 256) ws[i] = pw[i];
    __syncthreads();

    float xv[C];
    const float* xb = x + (size_t)b*C*HW + p;
#pragma unroll
    for (int ci = 0; ci < C; ci++) xv[ci] = xb[(size_t)ci*HW];

    float* outh = g_xph + ((size_t)b*HW + p)*C;
    float* outc = g_xp  + (size_t)b*C*HW + p;
#pragma unroll 1
    for (int co4 = 0; co4 < C; co4 += 4) {
        float a0 = pb[co4+0], a1 = pb[co4+1], a2 = pb[co4+2], a3 = pb[co4+3];
#pragma unroll
        for (int ci = 0; ci < C; ci++) {
            float v = xv[ci];
            a0 += ws[(co4+0)*C + ci] * v;
            a1 += ws[(co4+1)*C + ci] * v;
            a2 += ws[(co4+2)*C + ci] * v;
            a3 += ws[(co4+3)*C + ci] * v;
        }
        outc[(size_t)(co4+0)*HW] = a0;
        outc[(size_t)(co4+1)*HW] = a1;
        outc[(size_t)(co4+2)*HW] = a2;
        outc[(size_t)(co4+3)*HW] = a3;
        float4 r; r.x = a0; r.y = a1; r.z = a2; r.w = a3;
        *(float4*)(outh + co4) = r;
    }
}

// ---------------- K0: transpose reg_w -> [kk][ci][co] --------------------
__global__ void k0_wt(const float* __restrict__ rw)
{
    int i = blockIdx.x * 256 + threadIdx.x;
    if (i >= KK*C*CO) return;
    int co = i % CO;
    int ci = (i / CO) % C;
    int kk = i / (CO*C);
    g_wt[i] = rw[(co*C + ci)*KK + kk];
}

// ---------------- K2a: offset conv (18 ch) -> absolute coords ------------
__global__ __launch_bounds__(128) void k2_off(const float* __restrict__ ow,
                                              const float* __restrict__ ob)
{
    __shared__ float ws[18*C*KK];      // 41472 B
    int b = blockIdx.y, ho = blockIdx.x, wo = threadIdx.x;
    for (int i = threadIdx.x; i < 18*C*KK; i += 128) ws[i] = ow[i];
    __syncthreads();

    float acc[18];
#pragma unroll
    for (int j = 0; j < 18; j++) acc[j] = ob[j];

    const float* xb = g_xp + (size_t)b*C*HW;
    for (int ky = 0; ky < 3; ky++) {
        int y = ho - 1 + ky; if (y < 0 || y >= HH) continue;
        for (int kx = 0; kx < 3; kx++) {
            int xx = wo - 1 + kx; if (xx < 0 || xx >= WW) continue;
            int k = ky*3 + kx;
            const float* xp2 = xb + y*WW + xx;
#pragma unroll 4
            for (int ci = 0; ci < C; ci++) {
                float v = xp2[(size_t)ci*HW];
#pragma unroll
                for (int j = 0; j < 18; j++)
                    acc[j] += ws[(j*C + ci)*KK + k] * v;
            }
        }
    }
    int p = ho*WW + wo;
#pragma unroll
    for (int kk = 0; kk < KK; kk++) {
        float py = (float)(ho - 1 + kk/3) + acc[2*kk + 0];
        float px = (float)(wo - 1 + kk%3) + acc[2*kk + 1];
        g_py[((size_t)b*KK + kk)*HW + p] = py;
        g_px[((size_t)b*KK + kk)*HW + p] = px;
    }
}

// ---------------- K2b: mask conv (9 ch) -> 2*sigmoid ---------------------
__global__ __launch_bounds__(128) void k2_mask(const float* __restrict__ mw,
                                               const float* __restrict__ mb)
{
    __shared__ float ws[9*C*KK];       // 20736 B
    int b = blockIdx.y, ho = blockIdx.x, wo = threadIdx.x;
    for (int i = threadIdx.x; i < 9*C*KK; i += 128) ws[i] = mw[i];
    __syncthreads();

    float acc[9];
#pragma unroll
    for (int j = 0; j < 9; j++) acc[j] = mb[j];

    const float* xb = g_xp + (size_t)b*C*HW;
    for (int ky = 0; ky < 3; ky++) {
        int y = ho - 1 + ky; if (y < 0 || y >= HH) continue;
        for (int kx = 0; kx < 3; kx++) {
            int xx = wo - 1 + kx; if (xx < 0 || xx >= WW) continue;
            int k = ky*3 + kx;
            const float* xp2 = xb + y*WW + xx;
#pragma unroll 4
            for (int ci = 0; ci < C; ci++) {
                float v = xp2[(size_t)ci*HW];
#pragma unroll
                for (int j = 0; j < 9; j++)
                    acc[j] += ws[(j*C + ci)*KK + k] * v;
            }
        }
    }
    int p = ho*WW + wo;
#pragma unroll
    for (int kk = 0; kk < KK; kk++) {
        float z = acc[kk];
        g_m[((size_t)b*KK + kk)*HW + p] = 2.0f / (1.0f + expf(-z));
    }
}

// ---------------- K3: bilinear sample + modulate + GEMM (FFMA2) ----------
// block: 64 pixels x 128 couts, 256 threads.
// Register tile: 8 couts (as 4 packed co-pairs) x 4 pixels per thread.
__global__ __launch_bounds__(256) void k3_main(float* __restrict__ out)
{
    __shared__ float sS[C*64];     // [ci][px]   16384 B
    __shared__ float sW[C*CO];     // [ci][co]   32768 B  (total 49152 = 48K)

    int b   = blockIdx.y;
    int p0  = blockIdx.x * 64;
    int tid = threadIdx.x;
    int pxg = tid & 15;            // pixel group (4 pixels each)
    int cog = tid >> 4;            // cout group  (8 couts each)
    int pxl = tid >> 2;            // sampling: pixel 0..63
    int part = tid & 3;            // sampling: channel quarter

    // acc2[k][i]: packed pair (co = cog*8+2k, cog*8+2k+1), pixel i
    unsigned long long acc2[4][4];
#pragma unroll
    for (int k = 0; k < 4; k++)
#pragma unroll
        for (int i = 0; i < 4; i++) acc2[k][i] = 0ull;

    const float* xb = g_xph + (size_t)b*HW*C;

    for (int kk = 0; kk < KK; kk++) {
        __syncthreads();   // protect previous iteration's smem reads

        // --- load weight tile [ci][co] (coalesced from pre-transposed g_wt)
        {
            const float* wsrc = g_wt + kk*C*CO;
#pragma unroll
            for (int r = 0; r < 8; r++) {
                int idx = (tid + r*256) * 4;
                *(float4*)&sW[idx] = *(const float4*)&wsrc[idx];
            }
        }

        // --- bilinear sample 64 pixels x 64 channels into sS
        {
            int p = p0 + pxl;
            size_t o = ((size_t)b*KK + kk)*HW + p;
            float py = g_py[o], px = g_px[o], m = g_m[o];
            float y0f = floorf(py), x0f = floorf(px);
            float wy = py - y0f,   wx = px - x0f;
            int y0 = (int)y0f, x0 = (int)x0f;
            int y1 = y0 + 1,   x1 = x0 + 1;
            float vy0 = (y0 >= 0 && y0 < HH) ? 1.0f : 0.0f;
            float vy1 = (y1 >= 0 && y1 < HH) ? 1.0f : 0.0f;
            float vx0 = (x0 >= 0 && x0 < WW) ? 1.0f : 0.0f;
            float vx1 = (x1 >= 0 && x1 < WW) ? 1.0f : 0.0f;
            float w00 = (1.0f-wy)*(1.0f-wx)*vy0*vx0*m;
            float w01 = (1.0f-wy)*wx       *vy0*vx1*m;
            float w10 = wy*(1.0f-wx)       *vy1*vx0*m;
            float w11 = wy*wx              *vy1*vx1*m;
            int y0c = min(max(y0,0),HH-1), y1c = min(max(y1,0),HH-1);
            int x0c = min(max(x0,0),WW-1), x1c = min(max(x1,0),WW-1);
            const float* p00 = xb + ((size_t)y0c*WW + x0c)*C + part*16;
            const float* p01 = xb + ((size_t)y0c*WW + x1c)*C + part*16;
            const float* p10 = xb + ((size_t)y1c*WW + x0c)*C + part*16;
            const float* p11 = xb + ((size_t)y1c*WW + x1c)*C + part*16;
#pragma unroll
            for (int i = 0; i < 4; i++) {
                float4 a  = *(const float4*)(p00 + 4*i);
                float4 b4 = *(const float4*)(p01 + 4*i);
                float4 c  = *(const float4*)(p10 + 4*i);
                float4 d  = *(const float4*)(p11 + 4*i);
                int cib = part*16 + 4*i;
                sS[(cib+0)*64 + pxl] = w00*a.x + w01*b4.x + w10*c.x + w11*d.x;
                sS[(cib+1)*64 + pxl] = w00*a.y + w01*b4.y + w10*c.y + w11*d.y;
                sS[(cib+2)*64 + pxl] = w00*a.z + w01*b4.z + w10*c.z + w11*d.z;
                sS[(cib+3)*64 + pxl] = w00*a.w + w01*b4.w + w10*c.w + w11*d.w;
            }
        }
        __syncthreads();

        // --- GEMM microkernel (packed f32x2 over cout pairs):
        //     acc2[k][i] += W2[ci][copair k] * dup(S[ci][px i])
#pragma unroll 4
        for (int ci = 0; ci < C; ci++) {
            float4 s = *(const float4*)&sS[ci*64 + pxg*4];
            unsigned long long sd0 = f2_dup(s.x);
            unsigned long long sd1 = f2_dup(s.y);
            unsigned long long sd2 = f2_dup(s.z);
            unsigned long long sd3 = f2_dup(s.w);
            ulonglong2 wa = *(const ulonglong2*)&sW[ci*CO + cog*8];
            ulonglong2 wb = *(const ulonglong2*)&sW[ci*CO + cog*8 + 4];
            acc2[0][0] = f2_fma(wa.x, sd0, acc2[0][0]);
            acc2[0][1] = f2_fma(wa.x, sd1, acc2[0][1]);
            acc2[0][2] = f2_fma(wa.x, sd2, acc2[0][2]);
            acc2[0][3] = f2_fma(wa.x, sd3, acc2[0][3]);
            acc2[1][0] = f2_fma(wa.y, sd0, acc2[1][0]);
            acc2[1][1] = f2_fma(wa.y, sd1, acc2[1][1]);
            acc2[1][2] = f2_fma(wa.y, sd2, acc2[1][2]);
            acc2[1][3] = f2_fma(wa.y, sd3, acc2[1][3]);
            acc2[2][0] = f2_fma(wb.x, sd0, acc2[2][0]);
            acc2[2][1] = f2_fma(wb.x, sd1, acc2[2][1]);
            acc2[2][2] = f2_fma(wb.x, sd2, acc2[2][2]);
            acc2[2][3] = f2_fma(wb.x, sd3, acc2[2][3]);
            acc2[3][0] = f2_fma(wb.y, sd0, acc2[3][0]);
            acc2[3][1] = f2_fma(wb.y, sd1, acc2[3][1]);
            acc2[3][2] = f2_fma(wb.y, sd2, acc2[3][2]);
            acc2[3][3] = f2_fma(wb.y, sd3, acc2[3][3]);
        }
    }

    // --- epilogue: unpack co-pairs, write out[b][co][p] as float4 rows
#pragma unroll
    for (int k = 0; k < 4; k++) {
        float lo0, hi0, lo1, hi1, lo2, hi2, lo3, hi3;
        f2_unpack(acc2[k][0], lo0, hi0);
        f2_unpack(acc2[k][1], lo1, hi1);
        f2_unpack(acc2[k][2], lo2, hi2);
        f2_unpack(acc2[k][3], lo3, hi3);
        int co = cog*8 + 2*k;
        float4 rlo; rlo.x = lo0; rlo.y = lo1; rlo.z = lo2; rlo.w = lo3;
        float4 rhi; rhi.x = hi0; rhi.y = hi1; rhi.z = hi2; rhi.w = hi3;
        *(float4*)&out[((size_t)b*CO + co    )*HW + p0 + pxg*4] = rlo;
        *(float4*)&out[((size_t)b*CO + co + 1)*HW + p0 + pxg*4] = rhi;
    }
}

// ---------------- launch --------------------------------------------------
extern "C" void kernel_launch(void* const* d_in, const int* in_sizes, int n_in,
                              void* d_out, int out_size)
{
    const float* x     = (const float*)d_in[0];
    const float* pre_w = (const float*)d_in[1];
    const float* pre_b = (const float*)d_in[2];
    const float* off_w = (const float*)d_in[3];
    const float* off_b = (const float*)d_in[4];
    const float* mod_w = (const float*)d_in[5];
    const float* mod_b = (const float*)d_in[6];
    const float* reg_w = (const float*)d_in[7];
    float* out = (float*)d_out;

    k1_pre <<<dim3(HW/256, BB), 256>>>(x, pre_w, pre_b);
    k0_wt  <<<(KK*C*CO + 255)/256, 256>>>(reg_w);
    k2_off <<<dim3(HH, BB), 128>>>(off_w, off_b);
    k2_mask<<<dim3(HH, BB), 128>>>(mod_w, mod_b);
    k3_main<<<dim3(HW/64, BB), 256>>>(out);
}

// round 3
// speedup vs baseline: 1.0958x; 1.0958x over previous
#include <cuda_runtime.h>
#include <math.h>

#define BB 8
#define C  64
#define HH 128
#define WW 128
#define HW (HH*WW)
#define CO 128
#define KK 9
#define JCH 28                    // 18 offset + 9 mask + 1 pad
#define CW_SMEM (KK*C*JCH*4)      // 64512 B dynamic smem for combined conv

// ---------------- scratch (device globals; no allocation) ----------------
__device__ float g_xp [BB*C*HW];   // pre-conv output, NCHW
__device__ float g_xph[BB*HW*C];   // pre-conv output, NHWC (for gathers)
__device__ float g_py [BB*KK*HW];  // absolute sample y coord per (b,kk,pix)
__device__ float g_px [BB*KK*HW];  // absolute sample x coord
__device__ float g_m  [BB*KK*HW];  // modulation mask (2*sigmoid)
__device__ float g_wt [KK*C*CO];   // reg_w transposed to [kk][ci][co]
__device__ float g_cw [KK*C*JCH];  // packed off+mask weights [k][ci][j]
__device__ float g_cb [JCH];       // packed off+mask bias

// ---------------- packed f32x2 helpers (sm_100+ FFMA2 path) ---------------
__device__ __forceinline__ unsigned long long f2_fma(unsigned long long a,
                                                     unsigned long long b,
                                                     unsigned long long c)
{
    unsigned long long d;
    asm("fma.rn.f32x2 %0, %1, %2, %3;" : "=l"(d) : "l"(a), "l"(b), "l"(c));
    return d;
}
__device__ __forceinline__ unsigned long long f2_dup(float x)
{
    unsigned long long d;
    asm("mov.b64 %0, {%1, %1};" : "=l"(d) : "f"(x));
    return d;
}
__device__ __forceinline__ unsigned long long f2_pack(float lo, float hi)
{
    unsigned long long d;
    asm("mov.b64 %0, {%1, %2};" : "=l"(d) : "f"(lo), "f"(hi));
    return d;
}
__device__ __forceinline__ void f2_unpack(unsigned long long v, float& lo, float& hi)
{
    asm("mov.b64 {%0, %1}, %2;" : "=f"(lo), "=f"(hi) : "l"(v));
}

// ---------------- K0a: transpose reg_w -> [kk][ci][co] -------------------
__global__ void k0_wt(const float* __restrict__ rw)
{
    int i = blockIdx.x * 256 + threadIdx.x;
    if (i >= KK*C*CO) return;
    int co = i % CO;
    int ci = (i / CO) % C;
    int kk = i / (CO*C);
    g_wt[i] = rw[(co*C + ci)*KK + kk];
}

// ---------------- K0b: pack off+mask weights -> [k][ci][j(28)] -----------
__global__ void k0_cw(const float* __restrict__ ow, const float* __restrict__ ob,
                      const float* __restrict__ mw, const float* __restrict__ mb)
{
    int i = blockIdx.x * 256 + threadIdx.x;
    if (i < KK*C*JCH) {
        int j  = i % JCH;
        int ci = (i / JCH) % C;
        int k  = i / (JCH*C);
        float v = 0.0f;
        if (j < 18)      v = ow[(j*C + ci)*KK + k];
        else if (j < 27) v = mw[((j-18)*C + ci)*KK + k];
        g_cw[i] = v;
    }
    if (i < JCH) {
        float v = 0.0f;
        if (i < 18)      v = ob[i];
        else if (i < 27) v = mb[i-18];
        g_cb[i] = v;
    }
}

// ---------------- K1: 1x1 conv (packed FFMA2), write NCHW + NHWC ---------
__global__ __launch_bounds__(256) void k1_pre(const float* __restrict__ x,
                                              const float* __restrict__ pw,
                                              const float* __restrict__ pb)
{
    __shared__ float ws[C*C];          // transposed: [ci][co]
    int b = blockIdx.y;
    int p = blockIdx.x * 256 + threadIdx.x;
    for (int i = threadIdx.x; i < C*C; i += 256) {
        int ci = i >> 6, co = i & 63;
        ws[i] = pw[co*C + ci];
    }
    __syncthreads();

    float xv[C];
    const float* xb = x + (size_t)b*C*HW + p;
#pragma unroll
    for (int ci = 0; ci < C; ci++) xv[ci] = xb[(size_t)ci*HW];

    float* outh = g_xph + ((size_t)b*HW + p)*C;
    float* outc = g_xp  + (size_t)b*C*HW + p;

#pragma unroll 1
    for (int chunk = 0; chunk < 4; chunk++) {
        int co16 = chunk * 16;
        unsigned long long acc[8];
#pragma unroll
        for (int j = 0; j < 8; j++)
            acc[j] = f2_pack(pb[co16 + 2*j], pb[co16 + 2*j + 1]);
#pragma unroll 4
        for (int ci = 0; ci < C; ci++) {
            unsigned long long sd = f2_dup(xv[ci]);
            const float* wr = ws + ci*C + co16;
            ulonglong2 w0 = *(const ulonglong2*)(wr + 0);
            ulonglong2 w1 = *(const ulonglong2*)(wr + 4);
            ulonglong2 w2 = *(const ulonglong2*)(wr + 8);
            ulonglong2 w3 = *(const ulonglong2*)(wr + 12);
            acc[0] = f2_fma(w0.x, sd, acc[0]);
            acc[1] = f2_fma(w0.y, sd, acc[1]);
            acc[2] = f2_fma(w1.x, sd, acc[2]);
            acc[3] = f2_fma(w1.y, sd, acc[3]);
            acc[4] = f2_fma(w2.x, sd, acc[4]);
            acc[5] = f2_fma(w2.y, sd, acc[5]);
            acc[6] = f2_fma(w3.x, sd, acc[6]);
            acc[7] = f2_fma(w3.y, sd, acc[7]);
        }
        float o[16];
#pragma unroll
        for (int j = 0; j < 8; j++) f2_unpack(acc[j], o[2*j], o[2*j+1]);
#pragma unroll
        for (int q = 0; q < 4; q++) {
            float4 r; r.x = o[4*q]; r.y = o[4*q+1]; r.z = o[4*q+2]; r.w = o[4*q+3];
            *(float4*)(outh + co16 + 4*q) = r;
        }
#pragma unroll
        for (int j = 0; j < 16; j++)
            outc[(size_t)(co16 + j)*HW] = o[j];
    }
}

// ---------------- K2: combined offset+mask conv (packed FFMA2) -----------
__global__ __launch_bounds__(256) void k2_comb()
{
    extern __shared__ float ws[];      // [k][ci][28]  (64512 B dynamic)
    int b  = blockIdx.y;
    int ho = blockIdx.x*2 + (threadIdx.x >> 7);
    int wo = threadIdx.x & 127;

    for (int i = threadIdx.x; i < KK*C*JCH/4; i += 256)
        ((float4*)ws)[i] = ((const float4*)g_cw)[i];
    __syncthreads();

    unsigned long long acc[14];
#pragma unroll
    for (int jp = 0; jp < 14; jp++)
        acc[jp] = f2_pack(g_cb[2*jp], g_cb[2*jp+1]);

    const float* xb = g_xp + (size_t)b*C*HW;
#pragma unroll
    for (int ky = 0; ky < 3; ky++) {
        int y = ho - 1 + ky; if (y < 0 || y >= HH) continue;
#pragma unroll
        for (int kx = 0; kx < 3; kx++) {
            int xx = wo - 1 + kx; if (xx < 0 || xx >= WW) continue;
            const float* xp2 = xb + y*WW + xx;
            const float* wk  = ws + (ky*3 + kx)*C*JCH;
#pragma unroll 2
            for (int ci = 0; ci < C; ci++) {
                unsigned long long sd = f2_dup(xp2[(size_t)ci*HW]);
                const float* wr = wk + ci*JCH;
                ulonglong2 w0 = *(const ulonglong2*)(wr + 0);
                ulonglong2 w1 = *(const ulonglong2*)(wr + 4);
                ulonglong2 w2 = *(const ulonglong2*)(wr + 8);
                ulonglong2 w3 = *(const ulonglong2*)(wr + 12);
                ulonglong2 w4 = *(const ulonglong2*)(wr + 16);
                ulonglong2 w5 = *(const ulonglong2*)(wr + 20);
                ulonglong2 w6 = *(const ulonglong2*)(wr + 24);
                acc[0]  = f2_fma(w0.x, sd, acc[0]);
                acc[1]  = f2_fma(w0.y, sd, acc[1]);
                acc[2]  = f2_fma(w1.x, sd, acc[2]);
                acc[3]  = f2_fma(w1.y, sd, acc[3]);
                acc[4]  = f2_fma(w2.x, sd, acc[4]);
                acc[5]  = f2_fma(w2.y, sd, acc[5]);
                acc[6]  = f2_fma(w3.x, sd, acc[6]);
                acc[7]  = f2_fma(w3.y, sd, acc[7]);
                acc[8]  = f2_fma(w4.x, sd, acc[8]);
                acc[9]  = f2_fma(w4.y, sd, acc[9]);
                acc[10] = f2_fma(w5.x, sd, acc[10]);
                acc[11] = f2_fma(w5.y, sd, acc[11]);
                acc[12] = f2_fma(w6.x, sd, acc[12]);
                acc[13] = f2_fma(w6.y, sd, acc[13]);
            }
        }
    }

    float o[28];
#pragma unroll
    for (int jp = 0; jp < 14; jp++) f2_unpack(acc[jp], o[2*jp], o[2*jp+1]);

    int p = ho*WW + wo;
#pragma unroll
    for (int kk = 0; kk < KK; kk++) {
        float py = (float)(ho - 1 + kk/3) + o[2*kk + 0];
        float px = (float)(wo - 1 + kk%3) + o[2*kk + 1];
        g_py[((size_t)b*KK + kk)*HW + p] = py;
        g_px[((size_t)b*KK + kk)*HW + p] = px;
        g_m [((size_t)b*KK + kk)*HW + p] = 2.0f / (1.0f + expf(-o[18 + kk]));
    }
}

// ---------------- K3: bilinear sample + modulate + GEMM (FFMA2) ----------
__global__ __launch_bounds__(256) void k3_main(float* __restrict__ out)
{
    __shared__ float sS[C*64];     // [ci][px]   16384 B
    __shared__ float sW[C*CO];     // [ci][co]   32768 B  (total 49152 = 48K)

    int b   = blockIdx.y;
    int p0  = blockIdx.x * 64;
    int tid = threadIdx.x;
    int pxg = tid & 15;            // pixel group (4 pixels each)
    int cog = tid >> 4;            // cout group  (8 couts each)
    int pxl = tid >> 2;            // sampling: pixel 0..63
    int part = tid & 3;            // sampling: channel quarter

    unsigned long long acc2[4][4];
#pragma unroll
    for (int k = 0; k < 4; k++)
#pragma unroll
        for (int i = 0; i < 4; i++) acc2[k][i] = 0ull;

    const float* xb = g_xph + (size_t)b*HW*C;

    for (int kk = 0; kk < KK; kk++) {
        __syncthreads();   // protect previous iteration's smem reads

        {
            const float* wsrc = g_wt + kk*C*CO;
#pragma unroll
            for (int r = 0; r < 8; r++) {
                int idx = (tid + r*256) * 4;
                *(float4*)&sW[idx] = *(const float4*)&wsrc[idx];
            }
        }

        {
            int p = p0 + pxl;
            size_t o = ((size_t)b*KK + kk)*HW + p;
            float py = g_py[o], px = g_px[o], m = g_m[o];
            float y0f = floorf(py), x0f = floorf(px);
            float wy = py - y0f,   wx = px - x0f;
            int y0 = (int)y0f, x0 = (int)x0f;
            int y1 = y0 + 1,   x1 = x0 + 1;
            float vy0 = (y0 >= 0 && y0 < HH) ? 1.0f : 0.0f;
            float vy1 = (y1 >= 0 && y1 < HH) ? 1.0f : 0.0f;
            float vx0 = (x0 >= 0 && x0 < WW) ? 1.0f : 0.0f;
            float vx1 = (x1 >= 0 && x1 < WW) ? 1.0f : 0.0f;
            float w00 = (1.0f-wy)*(1.0f-wx)*vy0*vx0*m;
            float w01 = (1.0f-wy)*wx       *vy0*vx1*m;
            float w10 = wy*(1.0f-wx)       *vy1*vx0*m;
            float w11 = wy*wx              *vy1*vx1*m;
            int y0c = min(max(y0,0),HH-1), y1c = min(max(y1,0),HH-1);
            int x0c = min(max(x0,0),WW-1), x1c = min(max(x1,0),WW-1);
            const float* p00 = xb + ((size_t)y0c*WW + x0c)*C + part*16;
            const float* p01 = xb + ((size_t)y0c*WW + x1c)*C + part*16;
            const float* p10 = xb + ((size_t)y1c*WW + x0c)*C + part*16;
            const float* p11 = xb + ((size_t)y1c*WW + x1c)*C + part*16;
#pragma unroll
            for (int i = 0; i < 4; i++) {
                float4 a  = *(const float4*)(p00 + 4*i);
                float4 b4 = *(const float4*)(p01 + 4*i);
                float4 c  = *(const float4*)(p10 + 4*i);
                float4 d  = *(const float4*)(p11 + 4*i);
                int cib = part*16 + 4*i;
                sS[(cib+0)*64 + pxl] = w00*a.x + w01*b4.x + w10*c.x + w11*d.x;
                sS[(cib+1)*64 + pxl] = w00*a.y + w01*b4.y + w10*c.y + w11*d.y;
                sS[(cib+2)*64 + pxl] = w00*a.z + w01*b4.z + w10*c.z + w11*d.z;
                sS[(cib+3)*64 + pxl] = w00*a.w + w01*b4.w + w10*c.w + w11*d.w;
            }
        }
        __syncthreads();

#pragma unroll 4
        for (int ci = 0; ci < C; ci++) {
            float4 s = *(const float4*)&sS[ci*64 + pxg*4];
            unsigned long long sd0 = f2_dup(s.x);
            unsigned long long sd1 = f2_dup(s.y);
            unsigned long long sd2 = f2_dup(s.z);
            unsigned long long sd3 = f2_dup(s.w);
            ulonglong2 wa = *(const ulonglong2*)&sW[ci*CO + cog*8];
            ulonglong2 wb = *(const ulonglong2*)&sW[ci*CO + cog*8 + 4];
            acc2[0][0] = f2_fma(wa.x, sd0, acc2[0][0]);
            acc2[0][1] = f2_fma(wa.x, sd1, acc2[0][1]);
            acc2[0][2] = f2_fma(wa.x, sd2, acc2[0][2]);
            acc2[0][3] = f2_fma(wa.x, sd3, acc2[0][3]);
            acc2[1][0] = f2_fma(wa.y, sd0, acc2[1][0]);
            acc2[1][1] = f2_fma(wa.y, sd1, acc2[1][1]);
            acc2[1][2] = f2_fma(wa.y, sd2, acc2[1][2]);
            acc2[1][3] = f2_fma(wa.y, sd3, acc2[1][3]);
            acc2[2][0] = f2_fma(wb.x, sd0, acc2[2][0]);
            acc2[2][1] = f2_fma(wb.x, sd1, acc2[2][1]);
            acc2[2][2] = f2_fma(wb.x, sd2, acc2[2][2]);
            acc2[2][3] = f2_fma(wb.x, sd3, acc2[2][3]);
            acc2[3][0] = f2_fma(wb.y, sd0, acc2[3][0]);
            acc2[3][1] = f2_fma(wb.y, sd1, acc2[3][1]);
            acc2[3][2] = f2_fma(wb.y, sd2, acc2[3][2]);
            acc2[3][3] = f2_fma(wb.y, sd3, acc2[3][3]);
        }
    }

#pragma unroll
    for (int k = 0; k < 4; k++) {
        float lo0, hi0, lo1, hi1, lo2, hi2, lo3, hi3;
        f2_unpack(acc2[k][0], lo0, hi0);
        f2_unpack(acc2[k][1], lo1, hi1);
        f2_unpack(acc2[k][2], lo2, hi2);
        f2_unpack(acc2[k][3], lo3, hi3);
        int co = cog*8 + 2*k;
        float4 rlo; rlo.x = lo0; rlo.y = lo1; rlo.z = lo2; rlo.w = lo3;
        float4 rhi; rhi.x = hi0; rhi.y = hi1; rhi.z = hi2; rhi.w = hi3;
        *(float4*)&out[((size_t)b*CO + co    )*HW + p0 + pxg*4] = rlo;
        *(float4*)&out[((size_t)b*CO + co + 1)*HW + p0 + pxg*4] = rhi;
    }
}

// ---------------- launch --------------------------------------------------
extern "C" void kernel_launch(void* const* d_in, const int* in_sizes, int n_in,
                              void* d_out, int out_size)
{
    const float* x     = (const float*)d_in[0];
    const float* pre_w = (const float*)d_in[1];
    const float* pre_b = (const float*)d_in[2];
    const float* off_w = (const float*)d_in[3];
    const float* off_b = (const float*)d_in[4];
    const float* mod_w = (const float*)d_in[5];
    const float* mod_b = (const float*)d_in[6];
    const float* reg_w = (const float*)d_in[7];
    float* out = (float*)d_out;

    cudaFuncSetAttribute(k2_comb, cudaFuncAttributeMaxDynamicSharedMemorySize, CW_SMEM);

    k1_pre <<<dim3(HW/256, BB), 256>>>(x, pre_w, pre_b);
    k0_wt  <<<(KK*C*CO + 255)/256, 256>>>(reg_w);
    k0_cw  <<<(KK*C*JCH + 255)/256, 256>>>(off_w, off_b, mod_w, mod_b);
    k2_comb<<<dim3(HH/2, BB), 256, CW_SMEM>>>();
    k3_main<<<dim3(HW/64, BB), 256>>>(out);
}